// round 1
// baseline (speedup 1.0000x reference)
#include <cuda_runtime.h>
#include <cstdint>
#include <cstddef>

// Problem dims
#define Nn 256
#define Tt 128
#define Dd 512
#define Hh 1024
#define G4 4096            // 4*H
#define Ktot 2560          // H (h) + H (attn) + D (x_t)

// GEMM tiling
#define BM 128
#define BN 64
#define BK 16
#define APAD 4

// ---------------- scratch (device globals: allocation-free rule) ----------------
__device__ float g_h[Nn * Hh];
__device__ float g_c[Nn * Hh];
__device__ float g_attn[Nn * Hh];
__device__ float g_gates[(size_t)Nn * G4];

// ---------------- math helpers ----------------
__device__ __forceinline__ float sigmoidf_(float x) {
    return 1.0f / (1.0f + __expf(-x));
}
__device__ __forceinline__ float tanhf_(float x) {
    // accurate enough (~1e-6 rel) and robust at extremes
    float e = __expf(2.0f * x);
    return 1.0f - 2.0f / (e + 1.0f);
}

// packed f32x2 FMA (sm_100+): 2 FMAs per instruction, rt_SMSP=2 -> 128 FMA/cyc/SM
__device__ __forceinline__ unsigned long long dupf(float v) {
    unsigned long long d;
    unsigned int u = __float_as_uint(v);
    asm("mov.b64 %0, {%1, %1};" : "=l"(d) : "r"(u));
    return d;
}
__device__ __forceinline__ void ffma2(unsigned long long& a,
                                      unsigned long long x,
                                      unsigned long long y) {
    asm("fma.rn.f32x2 %0, %1, %2, %0;" : "+l"(a) : "l"(x), "l"(y));
}

// =====================================================================
// Per-step GEMM: gates[n, j] = [h | attn | x_t](n, :) @ [Wh; Wattn; Wx](:, j) + b[j]
// M=256, N=4096, K=2560. Grid (64, 2) = 128 blocks, 256 threads.
// =====================================================================
__global__ __launch_bounds__(256) void gemm_step_kernel(
    const float* __restrict__ x,
    const float* __restrict__ Wh,
    const float* __restrict__ Wattn,
    const float* __restrict__ Wx,
    const float* __restrict__ b,
    int t)
{
    __shared__ __align__(16) float As[BK][BM + APAD];
    __shared__ __align__(16) float Bs[BK][BN];

    const int tid = threadIdx.x;
    const int bm = blockIdx.y * BM;
    const int bn = blockIdx.x * BN;

    // A-tile loader: 2 float4 per thread (rows tid/4 and tid/4+64)
    const int arow = tid >> 2;
    const int acol = (tid & 3) * 4;
    // B-tile loader: 1 float4 per thread
    const int brow = tid >> 4;
    const int bcol = (tid & 15) * 4;
    // compute mapping: 16x16 thread grid, each thread -> 8(M) x 4(N) outputs
    const int tx = tid & 15;
    const int ty = tid >> 4;

    unsigned long long acc[4][4];
#pragma unroll
    for (int p = 0; p < 4; p++)
#pragma unroll
        for (int j = 0; j < 4; j++) acc[p][j] = 0ull;

    for (int k0 = 0; k0 < Ktot; k0 += BK) {
        // ---- load A tile (source switches by k-region; BK=16 never crosses boundaries) ----
#pragma unroll
        for (int r = 0; r < 2; r++) {
            int m = arow + r * 64;
            int gm = bm + m;
            const float* ap;
            if (k0 < Hh)          ap = g_h    + (size_t)gm * Hh + k0;
            else if (k0 < 2 * Hh) ap = g_attn + (size_t)gm * Hh + (k0 - Hh);
            else                  ap = x + (size_t)gm * (Tt * Dd) + (size_t)t * Dd + (k0 - 2 * Hh);
            float4 v = *(const float4*)(ap + acol);
            As[acol + 0][m] = v.x;
            As[acol + 1][m] = v.y;
            As[acol + 2][m] = v.z;
            As[acol + 3][m] = v.w;
        }
        // ---- load B tile ----
        {
            int k = k0 + brow;
            const float* bp;
            if (k < Hh)          bp = Wh    + (size_t)k * G4;
            else if (k < 2 * Hh) bp = Wattn + (size_t)(k - Hh) * G4;
            else                 bp = Wx    + (size_t)(k - 2 * Hh) * G4;
            *(float4*)&Bs[brow][bcol] = *(const float4*)(bp + bn + bcol);
        }
        __syncthreads();

#pragma unroll
        for (int k = 0; k < BK; k++) {
            // A as packed f32x2 pairs along M (contiguous in As[k][...])
            ulonglong2 a01 = *(const ulonglong2*)&As[k][ty * 8];
            ulonglong2 a23 = *(const ulonglong2*)&As[k][ty * 8 + 4];
            float4 bv = *(const float4*)&Bs[k][tx * 4];
            unsigned long long b0 = dupf(bv.x), b1 = dupf(bv.y);
            unsigned long long b2 = dupf(bv.z), b3 = dupf(bv.w);

            ffma2(acc[0][0], a01.x, b0); ffma2(acc[0][1], a01.x, b1);
            ffma2(acc[0][2], a01.x, b2); ffma2(acc[0][3], a01.x, b3);
            ffma2(acc[1][0], a01.y, b0); ffma2(acc[1][1], a01.y, b1);
            ffma2(acc[1][2], a01.y, b2); ffma2(acc[1][3], a01.y, b3);
            ffma2(acc[2][0], a23.x, b0); ffma2(acc[2][1], a23.x, b1);
            ffma2(acc[2][2], a23.x, b2); ffma2(acc[2][3], a23.x, b3);
            ffma2(acc[3][0], a23.y, b0); ffma2(acc[3][1], a23.y, b1);
            ffma2(acc[3][2], a23.y, b2); ffma2(acc[3][3], a23.y, b3);
        }
        __syncthreads();
    }

    // ---- epilogue: + bias, write gates ----
#pragma unroll
    for (int p = 0; p < 4; p++) {
        int m = bm + ty * 8 + 2 * p;
#pragma unroll
        for (int j = 0; j < 4; j++) {
            int col = bn + tx * 4 + j;
            float lo = __uint_as_float((unsigned int)(acc[p][j] & 0xffffffffull));
            float hi = __uint_as_float((unsigned int)(acc[p][j] >> 32));
            float bb = b[col];
            g_gates[(size_t)m * G4 + col]       = lo + bb;
            g_gates[(size_t)(m + 1) * G4 + col] = hi + bb;
        }
    }
}

// =====================================================================
// Attention over the 4x4 grid (block-per-n, 256 threads). hs = current h in smem.
// scores_l = (1/32) * sum_h A[n,h,l]*hs[h]; softmax over l; attn_h = sum_l A[n,h,l]*w_l
// =====================================================================
__device__ __forceinline__ void attention_block(int n, const float* __restrict__ A,
                                                const float* hs, float* attn_out, int tid)
{
    __shared__ float red[16][8];
    __shared__ float wsm[16];

    const float* An = A + (size_t)n * Hh * 16;

    float sc[16];
#pragma unroll
    for (int l = 0; l < 16; l++) sc[l] = 0.0f;

#pragma unroll
    for (int r = 0; r < 4; r++) {
        int hh = tid + r * 256;
        float hv = hs[hh];
        const float4* ar = (const float4*)(An + (size_t)hh * 16);
        float4 a0 = ar[0], a1 = ar[1], a2 = ar[2], a3 = ar[3];
        sc[0]  += a0.x * hv; sc[1]  += a0.y * hv; sc[2]  += a0.z * hv; sc[3]  += a0.w * hv;
        sc[4]  += a1.x * hv; sc[5]  += a1.y * hv; sc[6]  += a1.z * hv; sc[7]  += a1.w * hv;
        sc[8]  += a2.x * hv; sc[9]  += a2.y * hv; sc[10] += a2.z * hv; sc[11] += a2.w * hv;
        sc[12] += a3.x * hv; sc[13] += a3.y * hv; sc[14] += a3.z * hv; sc[15] += a3.w * hv;
    }
#pragma unroll
    for (int l = 0; l < 16; l++) {
#pragma unroll
        for (int off = 16; off > 0; off >>= 1)
            sc[l] += __shfl_xor_sync(0xffffffffu, sc[l], off);
    }
    int warp = tid >> 5, lane = tid & 31;
    if (lane == 0) {
#pragma unroll
        for (int l = 0; l < 16; l++) red[l][warp] = sc[l];
    }
    __syncthreads();
    if (tid == 0) {
        float s[16];
        float mx = -1e30f;
#pragma unroll
        for (int l = 0; l < 16; l++) {
            float v = 0.0f;
#pragma unroll
            for (int w = 0; w < 8; w++) v += red[l][w];
            v *= 0.03125f;  // 1/sqrt(1024)
            s[l] = v;
            mx = fmaxf(mx, v);
        }
        float sum = 0.0f;
#pragma unroll
        for (int l = 0; l < 16; l++) { float e = __expf(s[l] - mx); s[l] = e; sum += e; }
        float inv = 1.0f / sum;
#pragma unroll
        for (int l = 0; l < 16; l++) wsm[l] = s[l] * inv;
    }
    __syncthreads();

    float4 w0 = *(float4*)&wsm[0],  w1 = *(float4*)&wsm[4];
    float4 w2 = *(float4*)&wsm[8],  w3 = *(float4*)&wsm[12];
#pragma unroll
    for (int r = 0; r < 4; r++) {
        int hh = tid + r * 256;
        const float4* ar = (const float4*)(An + (size_t)hh * 16);
        float4 a0 = ar[0], a1 = ar[1], a2 = ar[2], a3 = ar[3];
        float v = a0.x * w0.x + a0.y * w0.y + a0.z * w0.z + a0.w * w0.w
                + a1.x * w1.x + a1.y * w1.y + a1.z * w1.z + a1.w * w1.w
                + a2.x * w2.x + a2.y * w2.y + a2.z * w2.z + a2.w * w2.w
                + a3.x * w3.x + a3.y * w3.y + a3.z * w3.z + a3.w * w3.w;
        attn_out[hh] = v;
    }
}

// =====================================================================
// Init: h0 = mean_l A[n,h,l]; c0 = h0; then attention for step 0.
// =====================================================================
__global__ __launch_bounds__(256) void init_kernel(const float* __restrict__ A)
{
    __shared__ float hs[Hh];
    int n = blockIdx.x;
    int tid = threadIdx.x;
    const float* An = A + (size_t)n * Hh * 16;

#pragma unroll
    for (int r = 0; r < 4; r++) {
        int hh = tid + r * 256;
        const float4* ar = (const float4*)(An + (size_t)hh * 16);
        float4 a0 = ar[0], a1 = ar[1], a2 = ar[2], a3 = ar[3];
        float s = a0.x + a0.y + a0.z + a0.w + a1.x + a1.y + a1.z + a1.w
                + a2.x + a2.y + a2.z + a2.w + a3.x + a3.y + a3.z + a3.w;
        s *= (1.0f / 16.0f);
        g_h[(size_t)n * Hh + hh] = s;
        g_c[(size_t)n * Hh + hh] = s;
        hs[hh] = s;
    }
    __syncthreads();
    attention_block(n, A, hs, g_attn + (size_t)n * Hh, tid);
}

// =====================================================================
// LSTM pointwise + next-step attention (fused). Block-per-n, 256 threads.
// =====================================================================
__global__ __launch_bounds__(256) void lstm_attn_kernel(const float* __restrict__ A,
                                                        float* __restrict__ out, int t)
{
    __shared__ float hs[Hh];
    int n = blockIdx.x;
    int tid = threadIdx.x;
    const float* gn = g_gates + (size_t)n * G4;

#pragma unroll
    for (int r = 0; r < 4; r++) {
        int hh = tid + r * 256;
        float iv = gn[hh];
        float fv = gn[Hh + hh];
        float ov = gn[2 * Hh + hh];
        float gv = gn[3 * Hh + hh];
        float c = g_c[(size_t)n * Hh + hh];
        float cn = sigmoidf_(fv) * c + sigmoidf_(iv) * tanhf_(gv);
        float hn = sigmoidf_(ov) * tanhf_(cn);
        g_c[(size_t)n * Hh + hh] = cn;
        g_h[(size_t)n * Hh + hh] = hn;
        out[(size_t)n * Tt * Hh + (size_t)t * Hh + hh] = hn;
        hs[hh] = hn;
    }
    __syncthreads();
    attention_block(n, A, hs, g_attn + (size_t)n * Hh, tid);
}

// =====================================================================
// launch
// =====================================================================
extern "C" void kernel_launch(void* const* d_in, const int* in_sizes, int n_in,
                              void* d_out, int out_size)
{
    (void)in_sizes; (void)n_in; (void)out_size;
    const float* x     = (const float*)d_in[0];  // (N, T, D)
    const float* A     = (const float*)d_in[1];  // (N, H, 4, 4)
    const float* Wx    = (const float*)d_in[2];  // (D, 4H)
    const float* Wh    = (const float*)d_in[3];  // (H, 4H)
    const float* Wattn = (const float*)d_in[4];  // (H, 4H)
    const float* b     = (const float*)d_in[5];  // (4H,)
    float* out = (float*)d_out;                  // (N, T, H)

    init_kernel<<<Nn, 256>>>(A);

    dim3 gemm_grid(G4 / BN, Nn / BM);  // (64, 2)
    for (int t = 0; t < Tt; t++) {
        gemm_step_kernel<<<gemm_grid, 256>>>(x, Wh, Wattn, Wx, b, t);
        lstm_attn_kernel<<<Nn, 256>>>(A, out, t);
    }
}

// round 2
// speedup vs baseline: 1.3038x; 1.3038x over previous
#include <cuda_runtime.h>
#include <cstdint>
#include <cstddef>

// Problem dims
#define Nn 256
#define Tt 128
#define Dd 512
#define Hh 1024
#define G4 4096            // 4*H
#define Ktot 2560          // H (h) + H (attn) + D (x_t)

// GEMM tiling
#define BM 128
#define BN 64
#define BK 16
#define APAD 4

// ---------------- scratch (device globals: allocation-free rule) ----------------
__device__ float g_h[Nn * Hh];
__device__ float g_c[Nn * Hh];
__device__ float g_attn[Nn * Hh];
__device__ float g_gates[(size_t)Nn * G4];

// ---------------- math helpers ----------------
__device__ __forceinline__ float sigmoidf_(float x) {
    return 1.0f / (1.0f + __expf(-x));
}
__device__ __forceinline__ float tanhf_(float x) {
    // accurate enough (~1e-6 rel) and robust at extremes
    float e = __expf(2.0f * x);
    return 1.0f - 2.0f / (e + 1.0f);
}

// packed f32x2 FMA (sm_100+): 2 FMAs per instruction, rt_SMSP=2 -> 128 FMA/cyc/SM
__device__ __forceinline__ unsigned long long dupf(float v) {
    unsigned long long d;
    unsigned int u = __float_as_uint(v);
    asm("mov.b64 %0, {%1, %1};" : "=l"(d) : "r"(u));
    return d;
}
__device__ __forceinline__ void ffma2(unsigned long long& a,
                                      unsigned long long x,
                                      unsigned long long y) {
    asm("fma.rn.f32x2 %0, %1, %2, %0;" : "+l"(a) : "l"(x), "l"(y));
}

// =====================================================================
// Per-step GEMM: gates[n, j] = [h | attn | x_t](n, :) @ [Wh; Wattn; Wx](:, j) + b[j]
// M=256, N=4096, K=2560. Grid (64, 2) = 128 blocks, 256 threads.
// =====================================================================
__global__ __launch_bounds__(256) void gemm_step_kernel(
    const float* __restrict__ x,
    const float* __restrict__ Wh,
    const float* __restrict__ Wattn,
    const float* __restrict__ Wx,
    const float* __restrict__ b,
    int t)
{
    __shared__ __align__(16) float As[BK][BM + APAD];
    __shared__ __align__(16) float Bs[BK][BN];

    const int tid = threadIdx.x;
    const int bm = blockIdx.y * BM;
    const int bn = blockIdx.x * BN;

    // A-tile loader: 2 float4 per thread (rows tid/4 and tid/4+64)
    const int arow = tid >> 2;
    const int acol = (tid & 3) * 4;
    // B-tile loader: 1 float4 per thread
    const int brow = tid >> 4;
    const int bcol = (tid & 15) * 4;
    // compute mapping: 16x16 thread grid, each thread -> 8(M) x 4(N) outputs
    const int tx = tid & 15;
    const int ty = tid >> 4;

    unsigned long long acc[4][4];
#pragma unroll
    for (int p = 0; p < 4; p++)
#pragma unroll
        for (int j = 0; j < 4; j++) acc[p][j] = 0ull;

    for (int k0 = 0; k0 < Ktot; k0 += BK) {
        // ---- load A tile (source switches by k-region; BK=16 never crosses boundaries) ----
#pragma unroll
        for (int r = 0; r < 2; r++) {
            int m = arow + r * 64;
            int gm = bm + m;
            const float* ap;
            if (k0 < Hh)          ap = g_h    + (size_t)gm * Hh + k0;
            else if (k0 < 2 * Hh) ap = g_attn + (size_t)gm * Hh + (k0 - Hh);
            else                  ap = x + (size_t)gm * (Tt * Dd) + (size_t)t * Dd + (k0 - 2 * Hh);
            float4 v = *(const float4*)(ap + acol);
            As[acol + 0][m] = v.x;
            As[acol + 1][m] = v.y;
            As[acol + 2][m] = v.z;
            As[acol + 3][m] = v.w;
        }
        // ---- load B tile ----
        {
            int k = k0 + brow;
            const float* bp;
            if (k < Hh)          bp = Wh    + (size_t)k * G4;
            else if (k < 2 * Hh) bp = Wattn + (size_t)(k - Hh) * G4;
            else                 bp = Wx    + (size_t)(k - 2 * Hh) * G4;
            *(float4*)&Bs[brow][bcol] = *(const float4*)(bp + bn + bcol);
        }
        __syncthreads();

#pragma unroll
        for (int k = 0; k < BK; k++) {
            // A as packed f32x2 pairs along M (contiguous in As[k][...])
            ulonglong2 a01 = *(const ulonglong2*)&As[k][ty * 8];
            ulonglong2 a23 = *(const ulonglong2*)&As[k][ty * 8 + 4];
            float4 bv = *(const float4*)&Bs[k][tx * 4];
            unsigned long long b0 = dupf(bv.x), b1 = dupf(bv.y);
            unsigned long long b2 = dupf(bv.z), b3 = dupf(bv.w);

            ffma2(acc[0][0], a01.x, b0); ffma2(acc[0][1], a01.x, b1);
            ffma2(acc[0][2], a01.x, b2); ffma2(acc[0][3], a01.x, b3);
            ffma2(acc[1][0], a01.y, b0); ffma2(acc[1][1], a01.y, b1);
            ffma2(acc[1][2], a01.y, b2); ffma2(acc[1][3], a01.y, b3);
            ffma2(acc[2][0], a23.x, b0); ffma2(acc[2][1], a23.x, b1);
            ffma2(acc[2][2], a23.x, b2); ffma2(acc[2][3], a23.x, b3);
            ffma2(acc[3][0], a23.y, b0); ffma2(acc[3][1], a23.y, b1);
            ffma2(acc[3][2], a23.y, b2); ffma2(acc[3][3], a23.y, b3);
        }
        __syncthreads();
    }

    // ---- epilogue: + bias, write gates ----
#pragma unroll
    for (int p = 0; p < 4; p++) {
        int m = bm + ty * 8 + 2 * p;
#pragma unroll
        for (int j = 0; j < 4; j++) {
            int col = bn + tx * 4 + j;
            float lo = __uint_as_float((unsigned int)(acc[p][j] & 0xffffffffull));
            float hi = __uint_as_float((unsigned int)(acc[p][j] >> 32));
            float bb = b[col];
            g_gates[(size_t)m * G4 + col]       = lo + bb;
            g_gates[(size_t)(m + 1) * G4 + col] = hi + bb;
        }
    }
}

// =====================================================================
// Attention over the 4x4 grid (block-per-n, 256 threads). hs = current h in smem.
// scores_l = (1/32) * sum_h A[n,h,l]*hs[h]; softmax over l; attn_h = sum_l A[n,h,l]*w_l
// =====================================================================
__device__ __forceinline__ void attention_block(int n, const float* __restrict__ A,
                                                const float* hs, float* attn_out, int tid)
{
    __shared__ float red[16][8];
    __shared__ float wsm[16];

    const float* An = A + (size_t)n * Hh * 16;

    float sc[16];
#pragma unroll
    for (int l = 0; l < 16; l++) sc[l] = 0.0f;

#pragma unroll
    for (int r = 0; r < 4; r++) {
        int hh = tid + r * 256;
        float hv = hs[hh];
        const float4* ar = (const float4*)(An + (size_t)hh * 16);
        float4 a0 = ar[0], a1 = ar[1], a2 = ar[2], a3 = ar[3];
        sc[0]  += a0.x * hv; sc[1]  += a0.y * hv; sc[2]  += a0.z * hv; sc[3]  += a0.w * hv;
        sc[4]  += a1.x * hv; sc[5]  += a1.y * hv; sc[6]  += a1.z * hv; sc[7]  += a1.w * hv;
        sc[8]  += a2.x * hv; sc[9]  += a2.y * hv; sc[10] += a2.z * hv; sc[11] += a2.w * hv;
        sc[12] += a3.x * hv; sc[13] += a3.y * hv; sc[14] += a3.z * hv; sc[15] += a3.w * hv;
    }
#pragma unroll
    for (int l = 0; l < 16; l++) {
#pragma unroll
        for (int off = 16; off > 0; off >>= 1)
            sc[l] += __shfl_xor_sync(0xffffffffu, sc[l], off);
    }
    int warp = tid >> 5, lane = tid & 31;
    if (lane == 0) {
#pragma unroll
        for (int l = 0; l < 16; l++) red[l][warp] = sc[l];
    }
    __syncthreads();
    if (tid == 0) {
        float s[16];
        float mx = -1e30f;
#pragma unroll
        for (int l = 0; l < 16; l++) {
            float v = 0.0f;
#pragma unroll
            for (int w = 0; w < 8; w++) v += red[l][w];
            v *= 0.03125f;  // 1/sqrt(1024)
            s[l] = v;
            mx = fmaxf(mx, v);
        }
        float sum = 0.0f;
#pragma unroll
        for (int l = 0; l < 16; l++) { float e = __expf(s[l] - mx); s[l] = e; sum += e; }
        float inv = 1.0f / sum;
#pragma unroll
        for (int l = 0; l < 16; l++) wsm[l] = s[l] * inv;
    }
    __syncthreads();

    float4 w0 = *(float4*)&wsm[0],  w1 = *(float4*)&wsm[4];
    float4 w2 = *(float4*)&wsm[8],  w3 = *(float4*)&wsm[12];
#pragma unroll
    for (int r = 0; r < 4; r++) {
        int hh = tid + r * 256;
        const float4* ar = (const float4*)(An + (size_t)hh * 16);
        float4 a0 = ar[0], a1 = ar[1], a2 = ar[2], a3 = ar[3];
        float v = a0.x * w0.x + a0.y * w0.y + a0.z * w0.z + a0.w * w0.w
                + a1.x * w1.x + a1.y * w1.y + a1.z * w1.z + a1.w * w1.w
                + a2.x * w2.x + a2.y * w2.y + a2.z * w2.z + a2.w * w2.w
                + a3.x * w3.x + a3.y * w3.y + a3.z * w3.z + a3.w * w3.w;
        attn_out[hh] = v;
    }
}

// =====================================================================
// Init: h0 = mean_l A[n,h,l]; c0 = h0; then attention for step 0.
// =====================================================================
__global__ __launch_bounds__(256) void init_kernel(const float* __restrict__ A)
{
    __shared__ float hs[Hh];
    int n = blockIdx.x;
    int tid = threadIdx.x;
    const float* An = A + (size_t)n * Hh * 16;

#pragma unroll
    for (int r = 0; r < 4; r++) {
        int hh = tid + r * 256;
        const float4* ar = (const float4*)(An + (size_t)hh * 16);
        float4 a0 = ar[0], a1 = ar[1], a2 = ar[2], a3 = ar[3];
        float s = a0.x + a0.y + a0.z + a0.w + a1.x + a1.y + a1.z + a1.w
                + a2.x + a2.y + a2.z + a2.w + a3.x + a3.y + a3.z + a3.w;
        s *= (1.0f / 16.0f);
        g_h[(size_t)n * Hh + hh] = s;
        g_c[(size_t)n * Hh + hh] = s;
        hs[hh] = s;
    }
    __syncthreads();
    attention_block(n, A, hs, g_attn + (size_t)n * Hh, tid);
}

// =====================================================================
// LSTM pointwise + next-step attention (fused). Block-per-n, 256 threads.
// =====================================================================
__global__ __launch_bounds__(256) void lstm_attn_kernel(const float* __restrict__ A,
                                                        float* __restrict__ out, int t)
{
    __shared__ float hs[Hh];
    int n = blockIdx.x;
    int tid = threadIdx.x;
    const float* gn = g_gates + (size_t)n * G4;

#pragma unroll
    for (int r = 0; r < 4; r++) {
        int hh = tid + r * 256;
        float iv = gn[hh];
        float fv = gn[Hh + hh];
        float ov = gn[2 * Hh + hh];
        float gv = gn[3 * Hh + hh];
        float c = g_c[(size_t)n * Hh + hh];
        float cn = sigmoidf_(fv) * c + sigmoidf_(iv) * tanhf_(gv);
        float hn = sigmoidf_(ov) * tanhf_(cn);
        g_c[(size_t)n * Hh + hh] = cn;
        g_h[(size_t)n * Hh + hh] = hn;
        out[(size_t)n * Tt * Hh + (size_t)t * Hh + hh] = hn;
        hs[hh] = hn;
    }
    __syncthreads();
    attention_block(n, A, hs, g_attn + (size_t)n * Hh, tid);
}

// =====================================================================
// launch
// =====================================================================
extern "C" void kernel_launch(void* const* d_in, const int* in_sizes, int n_in,
                              void* d_out, int out_size)
{
    (void)in_sizes; (void)n_in; (void)out_size;
    const float* x     = (const float*)d_in[0];  // (N, T, D)
    const float* A     = (const float*)d_in[1];  // (N, H, 4, 4)
    const float* Wx    = (const float*)d_in[2];  // (D, 4H)
    const float* Wh    = (const float*)d_in[3];  // (H, 4H)
    const float* Wattn = (const float*)d_in[4];  // (H, 4H)
    const float* b     = (const float*)d_in[5];  // (4H,)
    float* out = (float*)d_out;                  // (N, T, H)

    init_kernel<<<Nn, 256>>>(A);

    dim3 gemm_grid(G4 / BN, Nn / BM);  // (64, 2)
    for (int t = 0; t < Tt; t++) {
        gemm_step_kernel<<<gemm_grid, 256>>>(x, Wh, Wattn, Wx, b, t);
        lstm_attn_kernel<<<Nn, 256>>>(A, out, t);
    }
}